// round 5
// baseline (speedup 1.0000x reference)
#include <cuda_runtime.h>
#include <mma.h>
#include <math.h>

using namespace nvcuda;

// Problem constants (B=4, S=2048 -> T=8192 tokens)
#define HD    1024
#define ID    4096
#define NE    8
#define TTOK  8192
#define PAIRS (TTOK * 2)
#define PADM  128
#define CAP   (PAIRS + NE * PADM)   // 17408 padded pair rows

// GEMM tiling
#define BM  128
#define BN  64
#define BKK 16

// -------------------- device scratch (no allocations allowed) --------------------
__device__ int   g_topi[PAIRS];
__device__ float g_topw[PAIRS];
__device__ int   g_count[NE];
__device__ int   g_off[NE];
__device__ int   g_cursor[NE];
__device__ int   g_pair_token[CAP];
__device__ int   g_tok_pos[PAIRS];
__device__ float g_zsum;
__device__ float g_psum[NE];
__device__ float g_H[(size_t)CAP * ID];   // silu(gate)*up activations, per pair row
__device__ float g_P[(size_t)CAP * HD];   // per-pair down-proj output

__device__ __forceinline__ float clip10(float v) {
    return fminf(fmaxf(v, -10.0f), 10.0f);
}

// -------------------- 0: init accumulators + pair-list padding --------------------
__global__ void k_init() {
    int i = blockIdx.x * blockDim.x + threadIdx.x;
    if (i < CAP) g_pair_token[i] = 0;   // padding rows gather token 0 (harmless)
    if (i < NE) { g_count[i] = 0; g_cursor[i] = 0; g_psum[i] = 0.0f; }
    if (i == 0) g_zsum = 0.0f;
}

// -------------------- 1: router (one warp per token) --------------------
__global__ void k_router(const float* __restrict__ x, const float* __restrict__ rw) {
    int warp = threadIdx.x >> 5;
    int lane = threadIdx.x & 31;
    int t = blockIdx.x * 8 + warp;
    if (t >= TTOK) return;

    float acc[NE] = {0,0,0,0,0,0,0,0};
    const float* xr = x + (size_t)t * HD;
    for (int h = lane; h < HD; h += 32) {
        float xv = clip10(xr[h]);
        const float* r = rw + h * NE;
        #pragma unroll
        for (int e = 0; e < NE; e++) acc[e] += xv * r[e];
    }
    #pragma unroll
    for (int s = 16; s > 0; s >>= 1) {
        #pragma unroll
        for (int e = 0; e < NE; e++) acc[e] += __shfl_xor_sync(0xffffffffu, acc[e], s);
    }
    if (lane == 0) {
        float m = acc[0];
        #pragma unroll
        for (int e = 1; e < NE; e++) m = fmaxf(m, acc[e]);
        float p[NE];
        float se = 0.0f;
        #pragma unroll
        for (int e = 0; e < NE; e++) { p[e] = expf(acc[e] - m); se += p[e]; }
        float inv = 1.0f / se;
        #pragma unroll
        for (int e = 0; e < NE; e++) p[e] *= inv;
        float lse = m + logf(se);

        // top-1 / top-2 with first-index tie-break (matches jax top_k)
        int i1 = 0;
        #pragma unroll
        for (int e = 1; e < NE; e++) if (acc[e] > acc[i1]) i1 = e;
        int i2 = (i1 == 0) ? 1 : 0;
        #pragma unroll
        for (int e = 0; e < NE; e++) if (e != i1 && acc[e] > acc[i2]) i2 = e;

        float w1 = p[i1], w2 = p[i2];
        float ws = 1.0f / (w1 + w2);
        g_topi[t * 2 + 0] = i1;
        g_topi[t * 2 + 1] = i2;
        g_topw[t * 2 + 0] = w1 * ws;
        g_topw[t * 2 + 1] = w2 * ws;

        atomicAdd(&g_zsum, lse * lse);
        #pragma unroll
        for (int e = 0; e < NE; e++) atomicAdd(&g_psum[e], p[e]);
        atomicAdd(&g_count[i1], 1);
        atomicAdd(&g_count[i2], 1);
    }
}

// -------------------- 2: offsets + losses --------------------
__global__ void k_finalize(float* __restrict__ dout, int out_size) {
    if (threadIdx.x == 0 && blockIdx.x == 0) {
        int off = 0;
        float lb = 0.0f;
        for (int e = 0; e < NE; e++) {
            g_off[e] = off;
            int c = g_count[e];
            off += (c + PADM - 1) / PADM * PADM;
            lb += ((float)c * (1.0f / PAIRS)) * (g_psum[e] * (1.0f / TTOK));
        }
        lb *= 0.001f * NE;
        dout[out_size - 2] = lb;                       // lb_loss
        dout[out_size - 1] = g_zsum * (1.0f / TTOK);   // z_loss
    }
}

// -------------------- 3: scatter tokens into per-expert groups --------------------
__global__ void k_scatter() {
    int t = blockIdx.x * blockDim.x + threadIdx.x;
    if (t >= TTOK) return;
    #pragma unroll
    for (int k = 0; k < 2; k++) {
        int e = g_topi[t * 2 + k];
        int pos = g_off[e] + atomicAdd(&g_cursor[e], 1);
        g_pair_token[pos] = t;
        g_tok_pos[t * 2 + k] = pos;
    }
}

// -------------------- 4: grouped GEMM1: H = silu(X@Wg) * (X@Wu) --------------------
// grid (ID/BN=64, 64, NE), block 256
__global__ __launch_bounds__(256, 2)
void k_gemm1(const float* __restrict__ x,
             const float* __restrict__ wg,
             const float* __restrict__ wu) {
    int e = blockIdx.z;
    int cnt = g_count[e];
    int npad = (cnt + PADM - 1) & ~(PADM - 1);
    int m0 = blockIdx.y * BM;
    if (m0 >= npad) return;
    int base = g_off[e];
    int n0 = blockIdx.x * BN;

    __shared__ float As[BM][BKK + 4];
    __shared__ float Bg[BKK][BN + 4];
    __shared__ float Bu[BKK][BN + 4];
    __shared__ int   toks[BM];

    int tid = threadIdx.x;
    if (tid < BM) toks[tid] = g_pair_token[base + m0 + tid];
    __syncthreads();

    int warp = tid >> 5;
    int wm = warp & 3;   // 0..3 -> m offset wm*32
    int wn = warp >> 2;  // 0..1 -> n offset wn*32

    wmma::fragment<wmma::accumulator, 16, 16, 8, float> cg[2][2], cu[2][2];
    #pragma unroll
    for (int i = 0; i < 2; i++)
        #pragma unroll
        for (int j = 0; j < 2; j++) {
            wmma::fill_fragment(cg[i][j], 0.0f);
            wmma::fill_fragment(cu[i][j], 0.0f);
        }

    const float* wgp = wg + (size_t)e * HD * ID;
    const float* wup = wu + (size_t)e * HD * ID;

    int ar = tid >> 2;          // 0..63
    int ac = (tid & 3) * 4;     // 0,4,8,12
    int br = tid >> 4;          // 0..15
    int bc = (tid & 15) * 4;    // 0..60

    for (int k0 = 0; k0 < HD; k0 += BKK) {
        #pragma unroll
        for (int it = 0; it < 2; it++) {
            int r = ar + it * 64;
            float4 v = *(const float4*)(x + (size_t)toks[r] * HD + k0 + ac);
            As[r][ac + 0] = clip10(v.x);
            As[r][ac + 1] = clip10(v.y);
            As[r][ac + 2] = clip10(v.z);
            As[r][ac + 3] = clip10(v.w);
        }
        {
            float4 vg = *(const float4*)(wgp + (size_t)(k0 + br) * ID + n0 + bc);
            float4 vu = *(const float4*)(wup + (size_t)(k0 + br) * ID + n0 + bc);
            Bg[br][bc + 0] = vg.x; Bg[br][bc + 1] = vg.y; Bg[br][bc + 2] = vg.z; Bg[br][bc + 3] = vg.w;
            Bu[br][bc + 0] = vu.x; Bu[br][bc + 1] = vu.y; Bu[br][bc + 2] = vu.z; Bu[br][bc + 3] = vu.w;
        }
        __syncthreads();

        #pragma unroll
        for (int kk = 0; kk < BKK; kk += 8) {
            wmma::fragment<wmma::matrix_a, 16, 16, 8, wmma::precision::tf32, wmma::row_major> a[2];
            wmma::fragment<wmma::matrix_b, 16, 16, 8, wmma::precision::tf32, wmma::row_major> fg[2], fu[2];
            #pragma unroll
            for (int i = 0; i < 2; i++) {
                wmma::load_matrix_sync(a[i], &As[wm * 32 + i * 16][kk], BKK + 4);
                #pragma unroll
                for (int q = 0; q < a[i].num_elements; q++)
                    a[i].x[q] = wmma::__float_to_tf32(a[i].x[q]);
            }
            #pragma unroll
            for (int j = 0; j < 2; j++) {
                wmma::load_matrix_sync(fg[j], &Bg[kk][wn * 32 + j * 16], BN + 4);
                wmma::load_matrix_sync(fu[j], &Bu[kk][wn * 32 + j * 16], BN + 4);
                #pragma unroll
                for (int q = 0; q < fg[j].num_elements; q++) {
                    fg[j].x[q] = wmma::__float_to_tf32(fg[j].x[q]);
                    fu[j].x[q] = wmma::__float_to_tf32(fu[j].x[q]);
                }
            }
            #pragma unroll
            for (int i = 0; i < 2; i++)
                #pragma unroll
                for (int j = 0; j < 2; j++) {
                    wmma::mma_sync(cg[i][j], a[i], fg[j], cg[i][j]);
                    wmma::mma_sync(cu[i][j], a[i], fu[j], cu[i][j]);
                }
        }
        __syncthreads();
    }

    // epilogue: h = silu(g) * u; accumulator fragments of identical shape share layout
    #pragma unroll
    for (int i = 0; i < 2; i++)
        #pragma unroll
        for (int j = 0; j < 2; j++) {
            #pragma unroll
            for (int q = 0; q < cg[i][j].num_elements; q++) {
                float g = cg[i][j].x[q];
                float u = cu[i][j].x[q];
                cg[i][j].x[q] = (g / (1.0f + __expf(-g))) * u;
            }
            wmma::store_matrix_sync(
                g_H + (size_t)(base + m0 + wm * 32 + i * 16) * ID + n0 + wn * 32 + j * 16,
                cg[i][j], ID, wmma::mem_row_major);
        }
}

// -------------------- 5: grouped GEMM2: P = H @ Wd --------------------
// grid (HD/BN=16, 64, NE), block 256
__global__ __launch_bounds__(256, 2)
void k_gemm2(const float* __restrict__ wd) {
    int e = blockIdx.z;
    int cnt = g_count[e];
    int npad = (cnt + PADM - 1) & ~(PADM - 1);
    int m0 = blockIdx.y * BM;
    if (m0 >= npad) return;
    int base = g_off[e];
    int n0 = blockIdx.x * BN;

    __shared__ float As[BM][BKK + 4];
    __shared__ float Bs[BKK][BN + 4];

    int tid = threadIdx.x;
    int warp = tid >> 5;
    int wm = warp & 3;
    int wn = warp >> 2;

    wmma::fragment<wmma::accumulator, 16, 16, 8, float> c[2][2];
    #pragma unroll
    for (int i = 0; i < 2; i++)
        #pragma unroll
        for (int j = 0; j < 2; j++) wmma::fill_fragment(c[i][j], 0.0f);

    const float* wdp = wd + (size_t)e * ID * HD;

    int ar = tid >> 2;
    int ac = (tid & 3) * 4;
    int br = tid >> 4;
    int bc = (tid & 15) * 4;

    for (int k0 = 0; k0 < ID; k0 += BKK) {
        #pragma unroll
        for (int it = 0; it < 2; it++) {
            int r = ar + it * 64;
            float4 v = *(const float4*)(g_H + (size_t)(base + m0 + r) * ID + k0 + ac);
            As[r][ac + 0] = v.x; As[r][ac + 1] = v.y; As[r][ac + 2] = v.z; As[r][ac + 3] = v.w;
        }
        {
            float4 v = *(const float4*)(wdp + (size_t)(k0 + br) * HD + n0 + bc);
            Bs[br][bc + 0] = v.x; Bs[br][bc + 1] = v.y; Bs[br][bc + 2] = v.z; Bs[br][bc + 3] = v.w;
        }
        __syncthreads();

        #pragma unroll
        for (int kk = 0; kk < BKK; kk += 8) {
            wmma::fragment<wmma::matrix_a, 16, 16, 8, wmma::precision::tf32, wmma::row_major> a[2];
            wmma::fragment<wmma::matrix_b, 16, 16, 8, wmma::precision::tf32, wmma::row_major> b[2];
            #pragma unroll
            for (int i = 0; i < 2; i++) {
                wmma::load_matrix_sync(a[i], &As[wm * 32 + i * 16][kk], BKK + 4);
                #pragma unroll
                for (int q = 0; q < a[i].num_elements; q++)
                    a[i].x[q] = wmma::__float_to_tf32(a[i].x[q]);
            }
            #pragma unroll
            for (int j = 0; j < 2; j++) {
                wmma::load_matrix_sync(b[j], &Bs[kk][wn * 32 + j * 16], BN + 4);
                #pragma unroll
                for (int q = 0; q < b[j].num_elements; q++)
                    b[j].x[q] = wmma::__float_to_tf32(b[j].x[q]);
            }
            #pragma unroll
            for (int i = 0; i < 2; i++)
                #pragma unroll
                for (int j = 0; j < 2; j++)
                    wmma::mma_sync(c[i][j], a[i], b[j], c[i][j]);
        }
        __syncthreads();
    }

    #pragma unroll
    for (int i = 0; i < 2; i++)
        #pragma unroll
        for (int j = 0; j < 2; j++)
            wmma::store_matrix_sync(
                g_P + (size_t)(base + m0 + wm * 32 + i * 16) * HD + n0 + wn * 32 + j * 16,
                c[i][j], HD, wmma::mem_row_major);
}

// -------------------- 6: combine the two expert contributions + clip --------------------
__global__ void k_combine(float* __restrict__ out) {
    int gid = blockIdx.x * blockDim.x + threadIdx.x;  // one float4 per thread
    int t = gid >> 8;
    int c = (gid & 255) << 2;
    if (t >= TTOK) return;
    int p0 = g_tok_pos[t * 2 + 0];
    int p1 = g_tok_pos[t * 2 + 1];
    float w0 = g_topw[t * 2 + 0];
    float w1 = g_topw[t * 2 + 1];
    float4 a = *(const float4*)(g_P + (size_t)p0 * HD + c);
    float4 b = *(const float4*)(g_P + (size_t)p1 * HD + c);
    float4 o;
    o.x = clip10(w0 * a.x + w1 * b.x);
    o.y = clip10(w0 * a.y + w1 * b.y);
    o.z = clip10(w0 * a.z + w1 * b.z);
    o.w = clip10(w0 * a.w + w1 * b.w);
    *(float4*)(out + (size_t)t * HD + c) = o;
}

// -------------------- launch --------------------
extern "C" void kernel_launch(void* const* d_in, const int* in_sizes, int n_in,
                              void* d_out, int out_size) {
    const float* x  = (const float*)d_in[0];
    const float* rw = (const float*)d_in[1];
    const float* wg = (const float*)d_in[2];
    const float* wu = (const float*)d_in[3];
    const float* wd = (const float*)d_in[4];
    float* out = (float*)d_out;

    k_init<<<(CAP + 255) / 256, 256>>>();
    k_router<<<TTOK / 8, 256>>>(x, rw);
    k_finalize<<<1, 32>>>(out, out_size);
    k_scatter<<<(TTOK + 255) / 256, 256>>>();

    dim3 g1(ID / BN, TTOK / BM, NE);   // (64, 64, 8)
    k_gemm1<<<g1, 256>>>(x, wg, wu);

    dim3 g2(HD / BN, TTOK / BM, NE);   // (16, 64, 8)
    k_gemm2<<<g2, 256>>>(wd);

    k_combine<<<TTOK, 256>>>(out);     // 8192 blocks × 256 threads × float4
}

// round 9
// speedup vs baseline: 1.0777x; 1.0777x over previous
#include <cuda_runtime.h>
#include <mma.h>
#include <math.h>

using namespace nvcuda;

// Problem constants (B=4, S=2048 -> T=8192 tokens)
#define HD    1024
#define ID    4096
#define NE    8
#define TTOK  8192
#define PAIRS (TTOK * 2)
#define PADM  128
#define CAP   (PAIRS + NE * PADM)   // 17408 padded pair rows

// GEMM tiling
#define BM   128
#define BN   64
#define BKK  32
#define STG  3
#define LDA  (BKK + 4)   // 36 floats
#define LDB  (BN + 4)    // 68 floats
#define A_ELEMS (BM * LDA)    // 4608 floats per stage
#define B_ELEMS (BKK * LDB)   // 2176 floats per stage

#define SMEM1_BYTES ((STG * A_ELEMS + 2 * STG * B_ELEMS + 128) * 4)  // ~105.5 KB
#define SMEM2_BYTES ((STG * A_ELEMS + STG * B_ELEMS) * 4)            // ~81.4 KB

// -------------------- device scratch (no allocations allowed) --------------------
__device__ int   g_topi[PAIRS];
__device__ float g_topw[PAIRS];
__device__ int   g_count[NE];
__device__ int   g_off[NE];
__device__ int   g_cursor[NE];
__device__ int   g_pair_token[CAP];
__device__ int   g_tok_pos[PAIRS];
__device__ float g_zsum;
__device__ float g_psum[NE];
__device__ float g_X[(size_t)TTOK * HD];  // pre-clipped activations
__device__ float g_H[(size_t)CAP * ID];   // silu(gate)*up activations, per pair row
__device__ float g_P[(size_t)CAP * HD];   // per-pair down-proj output

__device__ __forceinline__ float clip10(float v) {
    return fminf(fmaxf(v, -10.0f), 10.0f);
}

// -------------------- cp.async helpers --------------------
__device__ __forceinline__ void cp_async16(void* smem_dst, const void* gsrc) {
    unsigned s = (unsigned)__cvta_generic_to_shared(smem_dst);
    asm volatile("cp.async.cg.shared.global [%0], [%1], 16;\n" :: "r"(s), "l"(gsrc));
}
__device__ __forceinline__ void cp_commit() {
    asm volatile("cp.async.commit_group;\n");
}
template<int N>
__device__ __forceinline__ void cp_wait() {
    asm volatile("cp.async.wait_group %0;\n" :: "n"(N));
}

// -------------------- 0: init accumulators + pair-list padding --------------------
__global__ void k_init() {
    int i = blockIdx.x * blockDim.x + threadIdx.x;
    if (i < CAP) g_pair_token[i] = 0;   // padding rows gather token 0 (harmless)
    if (i < NE) { g_count[i] = 0; g_cursor[i] = 0; g_psum[i] = 0.0f; }
    if (i == 0) g_zsum = 0.0f;
}

// -------------------- 0b: pre-clip X --------------------
// grid 8192 x 256 threads, one float4 each: covers TTOK*HD = 8M floats
__global__ void k_clip(const float* __restrict__ x) {
    size_t i = (size_t)blockIdx.x * blockDim.x + threadIdx.x;
    float4 v = ((const float4*)x)[i];
    v.x = clip10(v.x); v.y = clip10(v.y); v.z = clip10(v.z); v.w = clip10(v.w);
    ((float4*)g_X)[i] = v;
}

// -------------------- 1: router (one warp per token) --------------------
__global__ void k_router(const float* __restrict__ x, const float* __restrict__ rw) {
    int warp = threadIdx.x >> 5;
    int lane = threadIdx.x & 31;
    int t = blockIdx.x * 8 + warp;
    if (t >= TTOK) return;

    float acc[NE] = {0,0,0,0,0,0,0,0};
    const float* xr = x + (size_t)t * HD;
    for (int h = lane; h < HD; h += 32) {
        float xv = clip10(xr[h]);
        const float* r = rw + h * NE;
        #pragma unroll
        for (int e = 0; e < NE; e++) acc[e] += xv * r[e];
    }
    #pragma unroll
    for (int s = 16; s > 0; s >>= 1) {
        #pragma unroll
        for (int e = 0; e < NE; e++) acc[e] += __shfl_xor_sync(0xffffffffu, acc[e], s);
    }
    if (lane == 0) {
        float m = acc[0];
        #pragma unroll
        for (int e = 1; e < NE; e++) m = fmaxf(m, acc[e]);
        float p[NE];
        float se = 0.0f;
        #pragma unroll
        for (int e = 0; e < NE; e++) { p[e] = expf(acc[e] - m); se += p[e]; }
        float inv = 1.0f / se;
        #pragma unroll
        for (int e = 0; e < NE; e++) p[e] *= inv;
        float lse = m + logf(se);

        // top-1 / top-2 with first-index tie-break (matches jax top_k)
        int i1 = 0;
        #pragma unroll
        for (int e = 1; e < NE; e++) if (acc[e] > acc[i1]) i1 = e;
        int i2 = (i1 == 0) ? 1 : 0;
        #pragma unroll
        for (int e = 0; e < NE; e++) if (e != i1 && acc[e] > acc[i2]) i2 = e;

        float w1 = p[i1], w2 = p[i2];
        float ws = 1.0f / (w1 + w2);
        g_topi[t * 2 + 0] = i1;
        g_topi[t * 2 + 1] = i2;
        g_topw[t * 2 + 0] = w1 * ws;
        g_topw[t * 2 + 1] = w2 * ws;

        atomicAdd(&g_zsum, lse * lse);
        #pragma unroll
        for (int e = 0; e < NE; e++) atomicAdd(&g_psum[e], p[e]);
        atomicAdd(&g_count[i1], 1);
        atomicAdd(&g_count[i2], 1);
    }
}

// -------------------- 2: offsets + losses --------------------
__global__ void k_finalize(float* __restrict__ dout, int out_size) {
    if (threadIdx.x == 0 && blockIdx.x == 0) {
        int off = 0;
        float lb = 0.0f;
        for (int e = 0; e < NE; e++) {
            g_off[e] = off;
            int c = g_count[e];
            off += (c + PADM - 1) / PADM * PADM;
            lb += ((float)c * (1.0f / PAIRS)) * (g_psum[e] * (1.0f / TTOK));
        }
        lb *= 0.001f * NE;
        dout[out_size - 2] = lb;                       // lb_loss
        dout[out_size - 1] = g_zsum * (1.0f / TTOK);   // z_loss
    }
}

// -------------------- 3: scatter tokens into per-expert groups --------------------
__global__ void k_scatter() {
    int t = blockIdx.x * blockDim.x + threadIdx.x;
    if (t >= TTOK) return;
    #pragma unroll
    for (int k = 0; k < 2; k++) {
        int e = g_topi[t * 2 + k];
        int pos = g_off[e] + atomicAdd(&g_cursor[e], 1);
        g_pair_token[pos] = t;
        g_tok_pos[t * 2 + k] = pos;
    }
}

// -------------------- 4: grouped GEMM1: H = silu(X@Wg) * (X@Wu) --------------------
// 3-stage cp.async pipeline, BKK=32, one barrier per K-slice.
// grid (ID/BN=64, TTOK/BM=64, NE), block 256, dynamic smem SMEM1_BYTES
__global__ __launch_bounds__(256, 2)
void k_gemm1(const float* __restrict__ wg,
             const float* __restrict__ wu) {
    int e = blockIdx.z;
    int cnt = g_count[e];
    int npad = (cnt + PADM - 1) & ~(PADM - 1);
    int m0 = blockIdx.y * BM;
    if (m0 >= npad) return;
    int base = g_off[e];
    int n0 = blockIdx.x * BN;

    extern __shared__ float smem[];
    float* As = smem;                          // STG * A_ELEMS
    float* Bg = As + STG * A_ELEMS;            // STG * B_ELEMS
    float* Bu = Bg + STG * B_ELEMS;            // STG * B_ELEMS
    int*   toks = (int*)(Bu + STG * B_ELEMS);  // 128

    int tid = threadIdx.x;
    if (tid < BM) toks[tid] = g_pair_token[base + m0 + tid];
    __syncthreads();

    const float* wgp = wg + (size_t)e * HD * ID;
    const float* wup = wu + (size_t)e * HD * ID;
    const float* xg = g_X;

    auto load_stage = [&](int s, int k0) {
        float* as = As + s * A_ELEMS;
        float* bg = Bg + s * B_ELEMS;
        float* bu = Bu + s * B_ELEMS;
        #pragma unroll
        for (int it = 0; it < 4; it++) {           // A: 128x32 -> 1024 float4
            int idx = tid + it * 256;
            int r = idx >> 3;
            int c = (idx & 7) << 2;
            cp_async16(as + r * LDA + c, xg + (size_t)toks[r] * HD + k0 + c);
        }
        #pragma unroll
        for (int it = 0; it < 2; it++) {           // B: 32x64 each -> 512 float4 each
            int idx = tid + it * 256;
            int r = idx >> 4;
            int c = (idx & 15) << 2;
            cp_async16(bg + r * LDB + c, wgp + (size_t)(k0 + r) * ID + n0 + c);
            cp_async16(bu + r * LDB + c, wup + (size_t)(k0 + r) * ID + n0 + c);
        }
        cp_commit();
    };

    int warp = tid >> 5;
    int wm = warp & 3;   // m offset wm*32
    int wn = warp >> 2;  // n offset wn*32

    wmma::fragment<wmma::accumulator, 16, 16, 8, float> cg[2][2], cu[2][2];
    #pragma unroll
    for (int i = 0; i < 2; i++)
        #pragma unroll
        for (int j = 0; j < 2; j++) {
            wmma::fill_fragment(cg[i][j], 0.0f);
            wmma::fill_fragment(cu[i][j], 0.0f);
        }

    const int NIT = HD / BKK;   // 32
    load_stage(0, 0);
    load_stage(1, BKK);

    for (int i = 0; i < NIT; i++) {
        if (i + 2 < NIT) cp_wait<1>(); else cp_wait<0>();
        __syncthreads();
        if (i + 2 < NIT) load_stage((i + 2) % STG, (i + 2) * BKK);

        int s = i % STG;
        const float* as = As + s * A_ELEMS;
        const float* bgs = Bg + s * B_ELEMS;
        const float* bus = Bu + s * B_ELEMS;

        #pragma unroll
        for (int kk = 0; kk < BKK; kk += 8) {
            wmma::fragment<wmma::matrix_a, 16, 16, 8, wmma::precision::tf32, wmma::row_major> a[2];
            wmma::fragment<wmma::matrix_b, 16, 16, 8, wmma::precision::tf32, wmma::row_major> fg[2], fu[2];
            #pragma unroll
            for (int ii = 0; ii < 2; ii++) {
                wmma::load_matrix_sync(a[ii], as + (wm * 32 + ii * 16) * LDA + kk, LDA);
                #pragma unroll
                for (int q = 0; q < a[ii].num_elements; q++)
                    a[ii].x[q] = wmma::__float_to_tf32(a[ii].x[q]);
            }
            #pragma unroll
            for (int j = 0; j < 2; j++) {
                wmma::load_matrix_sync(fg[j], bgs + kk * LDB + wn * 32 + j * 16, LDB);
                wmma::load_matrix_sync(fu[j], bus + kk * LDB + wn * 32 + j * 16, LDB);
                #pragma unroll
                for (int q = 0; q < fg[j].num_elements; q++) {
                    fg[j].x[q] = wmma::__float_to_tf32(fg[j].x[q]);
                    fu[j].x[q] = wmma::__float_to_tf32(fu[j].x[q]);
                }
            }
            #pragma unroll
            for (int ii = 0; ii < 2; ii++)
                #pragma unroll
                for (int j = 0; j < 2; j++) {
                    wmma::mma_sync(cg[ii][j], a[ii], fg[j], cg[ii][j]);
                    wmma::mma_sync(cu[ii][j], a[ii], fu[j], cu[ii][j]);
                }
        }
    }

    // epilogue: h = silu(g) * u
    #pragma unroll
    for (int i = 0; i < 2; i++)
        #pragma unroll
        for (int j = 0; j < 2; j++) {
            #pragma unroll
            for (int q = 0; q < cg[i][j].num_elements; q++) {
                float g = cg[i][j].x[q];
                float u = cu[i][j].x[q];
                cg[i][j].x[q] = (g / (1.0f + __expf(-g))) * u;
            }
            wmma::store_matrix_sync(
                g_H + (size_t)(base + m0 + wm * 32 + i * 16) * ID + n0 + wn * 32 + j * 16,
                cg[i][j], ID, wmma::mem_row_major);
        }
}

// -------------------- 5: grouped GEMM2: P = H @ Wd --------------------
// grid (HD/BN=16, TTOK/BM=64, NE), block 256, dynamic smem SMEM2_BYTES
__global__ __launch_bounds__(256, 2)
void k_gemm2(const float* __restrict__ wd) {
    int e = blockIdx.z;
    int cnt = g_count[e];
    int npad = (cnt + PADM - 1) & ~(PADM - 1);
    int m0 = blockIdx.y * BM;
    if (m0 >= npad) return;
    int base = g_off[e];
    int n0 = blockIdx.x * BN;

    extern __shared__ float smem[];
    float* As = smem;
    float* Bs = As + STG * A_ELEMS;

    int tid = threadIdx.x;
    const float* wdp = wd + (size_t)e * ID * HD;
    const float* hrow = g_H + (size_t)(base + m0) * ID;

    auto load_stage = [&](int s, int k0) {
        float* as = As + s * A_ELEMS;
        float* bs = Bs + s * B_ELEMS;
        #pragma unroll
        for (int it = 0; it < 4; it++) {
            int idx = tid + it * 256;
            int r = idx >> 3;
            int c = (idx & 7) << 2;
            cp_async16(as + r * LDA + c, hrow + (size_t)r * ID + k0 + c);
        }
        #pragma unroll
        for (int it = 0; it < 2; it++) {
            int idx = tid + it * 256;
            int r = idx >> 4;
            int c = (idx & 15) << 2;
            cp_async16(bs + r * LDB + c, wdp + (size_t)(k0 + r) * HD + n0 + c);
        }
        cp_commit();
    };

    int warp = tid >> 5;
    int wm = warp & 3;
    int wn = warp >> 2;

    wmma::fragment<wmma::accumulator, 16, 16, 8, float> c[2][2];
    #pragma unroll
    for (int i = 0; i < 2; i++)
        #pragma unroll
        for (int j = 0; j < 2; j++) wmma::fill_fragment(c[i][j], 0.0f);

    const int NIT = ID / BKK;   // 128
    load_stage(0, 0);
    load_stage(1, BKK);

    for (int i = 0; i < NIT; i++) {
        if (i + 2 < NIT) cp_wait<1>(); else cp_wait<0>();
        __syncthreads();
        if (i + 2 < NIT) load_stage((i + 2) % STG, (i + 2) * BKK);

        int s = i % STG;
        const float* as = As + s * A_ELEMS;
        const float* bs = Bs + s * B_ELEMS;

        #pragma unroll
        for (int kk = 0; kk < BKK; kk += 8) {
            wmma::fragment<wmma::matrix_a, 16, 16, 8, wmma::precision::tf32, wmma::row_major> a[2];
            wmma::fragment<wmma::matrix_b, 16, 16, 8, wmma::precision::tf32, wmma::row_major> b[2];
            #pragma unroll
            for (int ii = 0; ii < 2; ii++) {
                wmma::load_matrix_sync(a[ii], as + (wm * 32 + ii * 16) * LDA + kk, LDA);
                #pragma unroll
                for (int q = 0; q < a[ii].num_elements; q++)
                    a[ii].x[q] = wmma::__float_to_tf32(a[ii].x[q]);
            }
            #pragma unroll
            for (int j = 0; j < 2; j++) {
                wmma::load_matrix_sync(b[j], bs + kk * LDB + wn * 32 + j * 16, LDB);
                #pragma unroll
                for (int q = 0; q < b[j].num_elements; q++)
                    b[j].x[q] = wmma::__float_to_tf32(b[j].x[q]);
            }
            #pragma unroll
            for (int ii = 0; ii < 2; ii++)
                #pragma unroll
                for (int j = 0; j < 2; j++)
                    wmma::mma_sync(c[ii][j], a[ii], b[j], c[ii][j]);
        }
    }

    #pragma unroll
    for (int i = 0; i < 2; i++)
        #pragma unroll
        for (int j = 0; j < 2; j++)
            wmma::store_matrix_sync(
                g_P + (size_t)(base + m0 + wm * 32 + i * 16) * HD + n0 + wn * 32 + j * 16,
                c[i][j], HD, wmma::mem_row_major);
}

// -------------------- 6: combine the two expert contributions + clip --------------------
__global__ void k_combine(float* __restrict__ out) {
    int gid = blockIdx.x * blockDim.x + threadIdx.x;  // one float4 per thread
    int t = gid >> 8;
    int c = (gid & 255) << 2;
    if (t >= TTOK) return;
    int p0 = g_tok_pos[t * 2 + 0];
    int p1 = g_tok_pos[t * 2 + 1];
    float w0 = g_topw[t * 2 + 0];
    float w1 = g_topw[t * 2 + 1];
    float4 a = *(const float4*)(g_P + (size_t)p0 * HD + c);
    float4 b = *(const float4*)(g_P + (size_t)p1 * HD + c);
    float4 o;
    o.x = clip10(w0 * a.x + w1 * b.x);
    o.y = clip10(w0 * a.y + w1 * b.y);
    o.z = clip10(w0 * a.z + w1 * b.z);
    o.w = clip10(w0 * a.w + w1 * b.w);
    *(float4*)(out + (size_t)t * HD + c) = o;
}

// -------------------- launch --------------------
extern "C" void kernel_launch(void* const* d_in, const int* in_sizes, int n_in,
                              void* d_out, int out_size) {
    const float* x  = (const float*)d_in[0];
    const float* rw = (const float*)d_in[1];
    const float* wg = (const float*)d_in[2];
    const float* wu = (const float*)d_in[3];
    const float* wd = (const float*)d_in[4];
    float* out = (float*)d_out;

    // attribute-only calls: no allocation, no stream work, capture-safe
    cudaFuncSetAttribute(k_gemm1, cudaFuncAttributeMaxDynamicSharedMemorySize, SMEM1_BYTES);
    cudaFuncSetAttribute(k_gemm2, cudaFuncAttributeMaxDynamicSharedMemorySize, SMEM2_BYTES);

    k_init<<<(CAP + 255) / 256, 256>>>();
    k_clip<<<TTOK, 256>>>(x);                      // 8192 blocks x 256 float4 = 8M floats
    k_router<<<TTOK / 8, 256>>>(x, rw);
    k_finalize<<<1, 32>>>(out, out_size);
    k_scatter<<<(TTOK + 255) / 256, 256>>>();

    dim3 g1(ID / BN, TTOK / BM, NE);   // (64, 64, 8)
    k_gemm1<<<g1, 256, SMEM1_BYTES>>>(wg, wu);

    dim3 g2(HD / BN, TTOK / BM, NE);   // (16, 64, 8)
    k_gemm2<<<g2, 256, SMEM2_BYTES>>>(wd);

    k_combine<<<TTOK, 256>>>(out);
}